// round 8
// baseline (speedup 1.0000x reference)
#include <cuda_runtime.h>
#include <math.h>

#define QLEN 1024
#define MLEN 1024
#define KLEN 2048
#define BSZ  4
#define DM   1024
#define NH   16
#define DH   64
#define SCALE 0.125f

// Scratch (device globals; no allocation allowed)
__device__ float g_Q [(size_t)BSZ*NH*QLEN*DH];   // [b][n][i][d]
__device__ float g_K [(size_t)BSZ*NH*KLEN*DH];   // [b][n][j][d]
__device__ float g_V [(size_t)BSZ*NH*KLEN*DH];   // [b][n][j][d]
__device__ float g_R [(size_t)NH*KLEN*DH];       // [n][p][d]
__device__ float g_AV[(size_t)QLEN*BSZ*DM];      // [i][b][n*64+d]
__device__ float g_AO[(size_t)QLEN*BSZ*DM];      // [i][b][c]

// ---------------------------------------------------------------------------
// Generic C = A @ B^T SGEMM, 128x128 tile, BK=8, 256 threads, 8x8 per thread,
// with register prefetch of the next K-slab.
// ---------------------------------------------------------------------------
template<int MODE>
__global__ void __launch_bounds__(256, 2) sgemm_kernel(
    const float* __restrict__ A, const float* __restrict__ B,
    const float* __restrict__ w, const float* __restrict__ mems, int K)
{
    __shared__ float As[8][128];
    __shared__ float Bs[8][128];
    const int tid = threadIdx.x;
    const int m0 = blockIdx.y * 128;
    const int n0 = blockIdx.x * 128;
    const int lrow = tid >> 1;          // 0..127
    const int lcol = (tid & 1) * 4;     // 0 or 4

    const float* aptr;
    if (MODE == 0) {
        int grow = m0 + lrow;
        int t = grow >> 2, b = grow & 3;
        aptr = (t < MLEN) ? (mems + ((size_t)t * BSZ + b) * DM)
                          : (w    + ((size_t)(t - MLEN) * BSZ + b) * DM);
    } else if (MODE == 2) {
        aptr = g_AV + (size_t)(m0 + lrow) * K;
    } else {
        aptr = A + (size_t)(m0 + lrow) * K;
    }
    const float* bptr = B + (size_t)(n0 + lrow) * K;

    const int tr = tid >> 4;   // 0..15
    const int tc = tid & 15;   // 0..15

    float acc[8][8];
#pragma unroll
    for (int i = 0; i < 8; i++)
#pragma unroll
        for (int j = 0; j < 8; j++) acc[i][j] = 0.f;

    float4 av = *(const float4*)(aptr + lcol);
    float4 bv = *(const float4*)(bptr + lcol);

    for (int k0 = 0; k0 < K; k0 += 8) {
        As[lcol + 0][lrow] = av.x; As[lcol + 1][lrow] = av.y;
        As[lcol + 2][lrow] = av.z; As[lcol + 3][lrow] = av.w;
        Bs[lcol + 0][lrow] = bv.x; Bs[lcol + 1][lrow] = bv.y;
        Bs[lcol + 2][lrow] = bv.z; Bs[lcol + 3][lrow] = bv.w;
        __syncthreads();
        if (k0 + 8 < K) {
            av = *(const float4*)(aptr + k0 + 8 + lcol);
            bv = *(const float4*)(bptr + k0 + 8 + lcol);
        }
#pragma unroll
        for (int k = 0; k < 8; k++) {
            float a[8], bb[8];
            *(float4*)(a)      = *(const float4*)&As[k][tr * 4];
            *(float4*)(a + 4)  = *(const float4*)&As[k][tr * 4 + 64];
            *(float4*)(bb)     = *(const float4*)&Bs[k][tc * 4];
            *(float4*)(bb + 4) = *(const float4*)&Bs[k][tc * 4 + 64];
#pragma unroll
            for (int i = 0; i < 8; i++)
#pragma unroll
                for (int j = 0; j < 8; j++) acc[i][j] += a[i] * bb[j];
        }
        __syncthreads();
    }

#pragma unroll
    for (int i = 0; i < 8; i++) {
        int gr = m0 + ((i < 4) ? tr * 4 + i : 64 + tr * 4 + i - 4);
#pragma unroll
        for (int j = 0; j < 8; j++) {
            int gc = n0 + ((j < 4) ? tc * 4 + j : 64 + tc * 4 + j - 4);
            float v = acc[i][j];
            if (MODE == 0) {
                int part = gc >> 10, hn = (gc >> 6) & 15, d = gc & 63;
                int t = gr >> 2, b = gr & 3;
                if (part == 0) {
                    if (t >= MLEN)
                        g_Q[(((size_t)(b * NH + hn)) * QLEN + (t - MLEN)) * DH + d] = v;
                } else if (part == 1) {
                    g_K[(((size_t)(b * NH + hn)) * KLEN + t) * DH + d] = v;
                } else {
                    g_V[(((size_t)(b * NH + hn)) * KLEN + t) * DH + d] = v;
                }
            } else if (MODE == 1) {
                int hn = gc >> 6, d = gc & 63;
                g_R[((size_t)hn * KLEN + gr) * DH + d] = v;
            } else {
                g_AO[(size_t)gr * DM + gc] = v;
            }
        }
    }
}

// ---------------------------------------------------------------------------
// Fused attention v4: 4x4 register blocking, stage1+stage2 fused in one
// d-loop (shared A-operand Qt), distributed c[p] GEMV, sliding BD window.
// Thread (tr,tc): rows i = tr*4..+3, cols j/d = tc*4..+3. Row softmax stats
// via 16-lane shuffles (xor 1,2,4,8) within the tr half-warp group.
// ---------------------------------------------------------------------------
#define SWZ(d) ((((d) >> 2) & 7) << 2)

__global__ void __launch_bounds__(256, 2) attn_kernel(
    const float* __restrict__ rwb, const float* __restrict__ rrb)
{
    extern __shared__ float sm[];
    float* Qt    = sm;               // [d][i^swz]  64*68
    float* Ks    = Qt + 64 * 68;     // [d][j^swz]  64*68
    float* Rs    = Ks + 64 * 68;     // [d][p^swz]  64*68   (aliased by Vs [j][d])
    float* Bh    = Rs + 64 * 68;     // [i][0..127] 64*132  (cols 0..63 also Ps)
    float* cs    = Bh + 64 * 132;    // [132]
    float* diffs = cs + 132;         // [64]
    float* Vs    = Rs;               // alias

    const int i0 = blockIdx.x * 64;
    const int bn = blockIdx.y;
    const int b = bn >> 4, n = bn & 15;
    const int tid = threadIdx.x;
    const int tr = tid >> 4;     // 0..15 : i rows tr*4..+3
    const int tc = tid & 15;     // 0..15 : j / d cols tc*4..+3

    const float* Qg = g_Q + ((size_t)bn * QLEN + i0) * DH;
    const float* Kg = g_K + (size_t)bn * KLEN * DH;
    const float* Vg = g_V + (size_t)bn * KLEN * DH;
    const float* Rg = g_R + (size_t)n * KLEN * DH;

    // ---- prologue: Qt (transposed, swizzled, bias+scale folded), diffs
    for (int vv = tid; vv < 64 * 64 / 4; vv += 256) {
        int idx = vv * 4, i = idx >> 6, d = idx & 63;   // d 4-aligned
        float4 q = *(const float4*)(Qg + i * DH + d);
        float4 u = *(const float4*)(rwb + n * DH + d);
        int ic = i ^ SWZ(d);
        Qt[(d + 0) * 68 + ic] = (q.x + u.x) * SCALE;
        Qt[(d + 1) * 68 + ic] = (q.y + u.y) * SCALE;
        Qt[(d + 2) * 68 + ic] = (q.z + u.z) * SCALE;
        Qt[(d + 3) * 68 + ic] = (q.w + u.w) * SCALE;
    }
    if (tid < 64) diffs[tid] = (rrb[n * DH + tid] - rwb[n * DH + tid]) * SCALE;

    const int rbase0 = QLEN - 64 - i0;   // rbase of tile 0, in [0, 960]
    for (int vv = tid; vv < 64 * 64 / 4; vv += 256) {
        int idx = vv * 4, rr = idx >> 6, d = idx & 63;
        float4 rv = *(const float4*)(Rg + (size_t)(rbase0 + rr) * DH + d);
        int rc = rr ^ SWZ(d);
        Rs[(d + 0) * 68 + rc] = rv.x; Rs[(d + 1) * 68 + rc] = rv.y;
        Rs[(d + 2) * 68 + rc] = rv.z; Rs[(d + 3) * 68 + rc] = rv.w;
    }
    __syncthreads();

    // ---- prime: Bh cols [64..127] = Qt . Rs(prime chunk); cs[64..127]
    {
        float acc[4][4];
#pragma unroll
        for (int ii = 0; ii < 4; ii++)
#pragma unroll
            for (int jj = 0; jj < 4; jj++) acc[ii][jj] = 0.f;
#pragma unroll 4
        for (int d = 0; d < 64; d++) {
            const int swz = SWZ(d);
            float4 a = *(const float4*)&Qt[d * 68 + ((tr * 4) ^ swz)];
            float4 r = *(const float4*)&Rs[d * 68 + ((tc * 4) ^ swz)];
            float av[4] = {a.x, a.y, a.z, a.w};
            float rv[4] = {r.x, r.y, r.z, r.w};
#pragma unroll
            for (int ii = 0; ii < 4; ii++)
#pragma unroll
                for (int jj = 0; jj < 4; jj++) acc[ii][jj] += av[ii] * rv[jj];
        }
#pragma unroll
        for (int ii = 0; ii < 4; ii++)
            *(float4*)&Bh[(tr * 4 + ii) * 132 + 64 + tc * 4] = *(float4*)&acc[ii][0];
        // cs: distributed GEMV, 4 threads per p
        int p = tid >> 2, seg = (tid & 3) * 16;
        float c = 0.f;
#pragma unroll 4
        for (int d = seg; d < seg + 16; d++)
            c += diffs[d] * Rs[d * 68 + (p ^ SWZ(d))];
        c += __shfl_xor_sync(0xffffffffu, c, 1);
        c += __shfl_xor_sync(0xffffffffu, c, 2);
        if ((tid & 3) == 0) cs[64 + p] = c;
    }

    float m[4], l[4], O[4][4];
#pragma unroll
    for (int ii = 0; ii < 4; ii++) {
        m[ii] = -1e30f; l[ii] = 0.f;
#pragma unroll
        for (int dd = 0; dd < 4; dd++) O[ii][dd] = 0.f;
    }

    const int njt = (MLEN + i0 + 63) / 64 + 1;

    for (int jt = 0; jt < njt; jt++) {
        const int j0 = jt * 64;
        const int rbase = j0 - i0 + (QLEN - 64);
        __syncthreads();   // prev PV done; Bh[64..127], cs[64..127] final

        // slide BD window: cols [0..63] <- [64..127]
        for (int vv = tid; vv < 1024; vv += 256) {
            int row = vv >> 4, cg = vv & 15;
            *(float4*)&Bh[row * 132 + cg * 4] =
                *(const float4*)&Bh[row * 132 + 64 + cg * 4];
        }
        if (tid < 64) cs[tid] = cs[64 + tid];

        // load K tile and next R chunk (rows rbase+64+rr)
        for (int vv = tid; vv < 64 * 64 / 4; vv += 256) {
            int idx = vv * 4, j = idx >> 6, d = idx & 63;
            float4 kv = *(const float4*)(Kg + (size_t)(j0 + j) * DH + d);
            int jc = j ^ SWZ(d);
            Ks[(d + 0) * 68 + jc] = kv.x; Ks[(d + 1) * 68 + jc] = kv.y;
            Ks[(d + 2) * 68 + jc] = kv.z; Ks[(d + 3) * 68 + jc] = kv.w;
        }
        for (int vv = tid; vv < 64 * 64 / 4; vv += 256) {
            int idx = vv * 4, rr = idx >> 6, d = idx & 63;
            int row = rbase + 64 + rr; if (row > KLEN - 1) row = KLEN - 1;
            float4 rv = *(const float4*)(Rg + (size_t)row * DH + d);
            int rc = rr ^ SWZ(d);
            Rs[(d + 0) * 68 + rc] = rv.x; Rs[(d + 1) * 68 + rc] = rv.y;
            Rs[(d + 2) * 68 + rc] = rv.z; Rs[(d + 3) * 68 + rc] = rv.w;
        }
        // prefetch V tile into registers (latency spans two barriers)
        float4 vreg[4];
#pragma unroll
        for (int u = 0; u < 4; u++) {
            int idx = (tid + u * 256) * 4, j = idx >> 6, d = idx & 63;
            vreg[u] = *(const float4*)(Vg + (size_t)(j0 + j) * DH + d);
        }
        __syncthreads();   // window slid, K/R loaded

        // ---- fused stage1+2: acc_s = Qt.K, acc_bd = Qt.R  (32 FMA / 3 LDS.128)
        float as4[4][4], ab4[4][4];
#pragma unroll
        for (int ii = 0; ii < 4; ii++)
#pragma unroll
            for (int jj = 0; jj < 4; jj++) { as4[ii][jj] = 0.f; ab4[ii][jj] = 0.f; }
#pragma unroll 4
        for (int d = 0; d < 64; d++) {
            const int swz = SWZ(d);
            float4 a = *(const float4*)&Qt[d * 68 + ((tr * 4) ^ swz)];
            float4 k = *(const float4*)&Ks[d * 68 + ((tc * 4) ^ swz)];
            float4 r = *(const float4*)&Rs[d * 68 + ((tc * 4) ^ swz)];
            float av[4] = {a.x, a.y, a.z, a.w};
            float kv[4] = {k.x, k.y, k.z, k.w};
            float rv[4] = {r.x, r.y, r.z, r.w};
#pragma unroll
            for (int ii = 0; ii < 4; ii++)
#pragma unroll
                for (int jj = 0; jj < 4; jj++) {
                    as4[ii][jj] += av[ii] * kv[jj];
                    ab4[ii][jj] += av[ii] * rv[jj];
                }
        }
#pragma unroll
        for (int ii = 0; ii < 4; ii++)
            *(float4*)&Bh[(tr * 4 + ii) * 132 + 64 + tc * 4] = *(float4*)&ab4[ii][0];
        {   // cs for new columns
            int p = tid >> 2, seg = (tid & 3) * 16;
            float c = 0.f;
#pragma unroll 4
            for (int d = seg; d < seg + 16; d++)
                c += diffs[d] * Rs[d * 68 + (p ^ SWZ(d))];
            c += __shfl_xor_sync(0xffffffffu, c, 1);
            c += __shfl_xor_sync(0xffffffffu, c, 2);
            if ((tid & 3) == 0) cs[64 + p] = c;
        }
        __syncthreads();   // Bh/cs window complete; Rs free

        // store V tile (Vs aliases Rs)
#pragma unroll
        for (int u = 0; u < 4; u++) {
            int idx = (tid + u * 256) * 4, j = idx >> 6, d = idx & 63;
            *(float4*)&Vs[j * 68 + d] = vreg[u];
        }

        // ---- gather rel-shifted BD + c, mask, online softmax
        float S[4][4];
#pragma unroll
        for (int ii = 0; ii < 4; ii++) {
            const int i = tr * 4 + ii;
            const float* bh = Bh + i * 132;
#pragma unroll
            for (int jj = 0; jj < 4; jj++) {
                int pl = tc * 4 + jj + 63 - i;
                S[ii][jj] = as4[ii][jj] + bh[pl] + cs[pl];
            }
        }
        if (j0 + 63 > MLEN + i0) {
#pragma unroll
            for (int ii = 0; ii < 4; ii++) {
                const int lim = MLEN + i0 + tr * 4 + ii - j0;
#pragma unroll
                for (int jj = 0; jj < 4; jj++)
                    if (tc * 4 + jj > lim) S[ii][jj] = -1e30f;
            }
        }
#pragma unroll
        for (int ii = 0; ii < 4; ii++) {
            float t = fmaxf(fmaxf(S[ii][0], S[ii][1]), fmaxf(S[ii][2], S[ii][3]));
            t = fmaxf(t, __shfl_xor_sync(0xffffffffu, t, 1));
            t = fmaxf(t, __shfl_xor_sync(0xffffffffu, t, 2));
            t = fmaxf(t, __shfl_xor_sync(0xffffffffu, t, 4));
            t = fmaxf(t, __shfl_xor_sync(0xffffffffu, t, 8));
            float mnew = fmaxf(m[ii], t);
            float corr = __expf(m[ii] - mnew);
            float s0 = 0.f;
#pragma unroll
            for (int jj = 0; jj < 4; jj++) {
                float p = __expf(S[ii][jj] - mnew); S[ii][jj] = p; s0 += p;
            }
            s0 += __shfl_xor_sync(0xffffffffu, s0, 1);
            s0 += __shfl_xor_sync(0xffffffffu, s0, 2);
            s0 += __shfl_xor_sync(0xffffffffu, s0, 4);
            s0 += __shfl_xor_sync(0xffffffffu, s0, 8);
            l[ii] = l[ii] * corr + s0;
            m[ii] = mnew;
#pragma unroll
            for (int dd = 0; dd < 4; dd++) O[ii][dd] *= corr;
        }

        // publish P into Bh cols [0..63] (row group = 16 contiguous lanes)
        __syncwarp();
#pragma unroll
        for (int ii = 0; ii < 4; ii++)
            *(float4*)&Bh[(tr * 4 + ii) * 132 + tc * 4] = *(float4*)&S[ii][0];
        __syncthreads();   // Vs + P ready

        // ---- PV: O[ii][dd] += P[i][j] * V[j][d]
#pragma unroll 2
        for (int j = 0; j < 64; j++) {
            float4 vv4 = *(const float4*)&Vs[j * 68 + tc * 4];
            float p0 = Bh[(tr * 4 + 0) * 132 + j];
            float p1 = Bh[(tr * 4 + 1) * 132 + j];
            float p2 = Bh[(tr * 4 + 2) * 132 + j];
            float p3 = Bh[(tr * 4 + 3) * 132 + j];
            O[0][0] += p0 * vv4.x; O[0][1] += p0 * vv4.y; O[0][2] += p0 * vv4.z; O[0][3] += p0 * vv4.w;
            O[1][0] += p1 * vv4.x; O[1][1] += p1 * vv4.y; O[1][2] += p1 * vv4.z; O[1][3] += p1 * vv4.w;
            O[2][0] += p2 * vv4.x; O[2][1] += p2 * vv4.y; O[2][2] += p2 * vv4.z; O[2][3] += p2 * vv4.w;
            O[3][0] += p3 * vv4.x; O[3][1] += p3 * vv4.y; O[3][2] += p3 * vv4.z; O[3][3] += p3 * vv4.w;
        }
    }

#pragma unroll
    for (int ii = 0; ii < 4; ii++) {
        const float inv = 1.f / l[ii];
        const int ig = i0 + tr * 4 + ii;
        float* op = g_AV + ((size_t)ig * BSZ + b) * DM + n * DH + tc * 4;
        *(float4*)op = make_float4(O[ii][0]*inv, O[ii][1]*inv, O[ii][2]*inv, O[ii][3]*inv);
    }
}

// ---------------------------------------------------------------------------
// Residual + LayerNorm: out = LN(w + attn_out) * g + b; one block per row.
// ---------------------------------------------------------------------------
__global__ void __launch_bounds__(256) ln_kernel(
    const float* __restrict__ w, const float* __restrict__ g,
    const float* __restrict__ beta, float* __restrict__ out)
{
    const int row = blockIdx.x;
    const float* ao = g_AO + (size_t)row * DM;
    const float* wr = w    + (size_t)row * DM;
    const int tid = threadIdx.x;
    float x[4];
    float s = 0.f, ss = 0.f;
#pragma unroll
    for (int v = 0; v < 4; v++) {
        int c = tid + v * 256;
        float val = wr[c] + ao[c];
        x[v] = val; s += val; ss += val * val;
    }
#pragma unroll
    for (int o = 16; o; o >>= 1) {
        s  += __shfl_xor_sync(0xffffffffu, s,  o);
        ss += __shfl_xor_sync(0xffffffffu, ss, o);
    }
    __shared__ float sA[8], sB[8];
    int wid = tid >> 5, lane = tid & 31;
    if (lane == 0) { sA[wid] = s; sB[wid] = ss; }
    __syncthreads();
    if (wid == 0) {
        s  = (lane < 8) ? sA[lane] : 0.f;
        ss = (lane < 8) ? sB[lane] : 0.f;
#pragma unroll
        for (int o = 4; o; o >>= 1) {
            s  += __shfl_xor_sync(0xffffffffu, s,  o);
            ss += __shfl_xor_sync(0xffffffffu, ss, o);
        }
        if (lane == 0) { sA[0] = s; sB[0] = ss; }
    }
    __syncthreads();
    const float mu  = sA[0] * (1.f / DM);
    const float var = sB[0] * (1.f / DM) - mu * mu;
    const float rstd = rsqrtf(var + 1e-5f);
#pragma unroll
    for (int v = 0; v < 4; v++) {
        int c = tid + v * 256;
        out[(size_t)row * DM + c] = (x[v] - mu) * rstd * g[c] + beta[c];
    }
}

extern "C" void kernel_launch(void* const* d_in, const int* in_sizes, int n_in,
                              void* d_out, int out_size)
{
    const float* w     = (const float*)d_in[0];
    const float* r     = (const float*)d_in[1];
    const float* mems  = (const float*)d_in[2];
    // d_in[3] = attn_mask: analytic (j > MLEN + i), never read
    const float* qkv_w = (const float*)d_in[4];
    const float* r_w   = (const float*)d_in[5];
    const float* o_w   = (const float*)d_in[6];
    const float* rwb   = (const float*)d_in[7];
    const float* rrb   = (const float*)d_in[8];
    const float* ln_g  = (const float*)d_in[9];
    const float* ln_b  = (const float*)d_in[10];
    float* out = (float*)d_out;

    // 1) QKV projection over concat(mems, w)
    sgemm_kernel<0><<<dim3(3072 / 128, (KLEN * BSZ) / 128), 256>>>(
        nullptr, qkv_w, w, mems, DM);
    // 2) relative-position keys
    sgemm_kernel<1><<<dim3(DM / 128, KLEN / 128), 256>>>(
        r, r_w, nullptr, nullptr, DM);
    // 3) fused attention
    const int shmem = (64 * 68 * 3 + 64 * 132 + 132 + 64) * 4;  // 86800 B
    cudaFuncSetAttribute(attn_kernel, cudaFuncAttributeMaxDynamicSharedMemorySize, shmem);
    attn_kernel<<<dim3(QLEN / 64, BSZ * NH), 256, shmem>>>(rwb, rrb);
    // 4) output projection
    sgemm_kernel<2><<<dim3(DM / 128, (QLEN * BSZ) / 128), 256>>>(
        nullptr, o_w, nullptr, nullptr, DM);
    // 5) residual + LayerNorm
    ln_kernel<<<QLEN * BSZ, 256>>>(w, ln_g, ln_b, out);
}

// round 9
// speedup vs baseline: 1.3787x; 1.3787x over previous
#include <cuda_runtime.h>
#include <math.h>
#include <stdint.h>

#define QLEN 1024
#define MLEN 1024
#define KLEN 2048
#define BSZ  4
#define DM   1024
#define NH   16
#define DH   64
#define SCALE 0.125f

// Scratch (device globals; no allocation allowed)
__device__ float g_Q [(size_t)BSZ*NH*QLEN*DH];   // [b][n][i][d]
__device__ float g_K [(size_t)BSZ*NH*KLEN*DH];   // [b][n][j][d]
__device__ float g_V [(size_t)BSZ*NH*KLEN*DH];   // [b][n][j][d]
__device__ float g_R [(size_t)NH*KLEN*DH];       // [n][p][d]
__device__ float g_AV[(size_t)QLEN*BSZ*DM];      // [i][b][n*64+d]
__device__ float g_AO[(size_t)QLEN*BSZ*DM];      // [i][b][c]

__device__ __forceinline__ uint32_t f2tf32(float x) {
    uint32_t u;
    asm("cvt.rna.tf32.f32 %0, %1;" : "=r"(u) : "f"(x));
    return u;
}

__device__ __forceinline__ void mma_tf32(float* c, const uint32_t* a, const uint32_t* b) {
    asm volatile(
        "mma.sync.aligned.m16n8k8.row.col.f32.tf32.tf32.f32 "
        "{%0,%1,%2,%3}, {%4,%5,%6,%7}, {%8,%9}, {%0,%1,%2,%3};"
        : "+f"(c[0]), "+f"(c[1]), "+f"(c[2]), "+f"(c[3])
        : "r"(a[0]), "r"(a[1]), "r"(a[2]), "r"(a[3]), "r"(b[0]), "r"(b[1]));
}

// ---------------------------------------------------------------------------
// TF32 tensor-core GEMM: C = A @ B^T. CTA tile 128x64, BK=32, 256 threads,
// 8 warps in 4(m) x 2(n) grid, each warp 32x32 via m16n8k8 mma (2 mt x 4 nt).
// Smem stride 36 words -> conflict-free fragment loads.
// MODE 0: A = virtual concat(mems, w), B = qkv_w; scatter to Q/K/V
// MODE 1: A = r, B = r_w; scatter to g_R
// MODE 2: A = g_AV, B = o_w; write g_AO
// ---------------------------------------------------------------------------
template<int MODE>
__global__ void __launch_bounds__(256, 2) tgemm_kernel(
    const float* __restrict__ A, const float* __restrict__ B,
    const float* __restrict__ w, const float* __restrict__ mems, int K)
{
    __shared__ uint32_t As[128][36];
    __shared__ uint32_t Bs[64][36];
    const int tid = threadIdx.x;
    const int m0 = blockIdx.y * 128;
    const int n0 = blockIdx.x * 64;

    // ---- global load assignment (float4 granularity)
    // A tile: 128 rows x 32 k = 1024 float4 -> 4 per thread
    // B tile:  64 rows x 32 k =  512 float4 -> 2 per thread
    const float* aptr[4]; int arow[4], akc[4];
#pragma unroll
    for (int v = 0; v < 4; v++) {
        int idx = tid + v * 256;
        arow[v] = idx >> 3; akc[v] = (idx & 7) * 4;
        int grow = m0 + arow[v];
        if (MODE == 0) {
            int t = grow >> 2, b = grow & 3;
            aptr[v] = (t < MLEN) ? (mems + ((size_t)t * BSZ + b) * DM)
                                 : (w    + ((size_t)(t - MLEN) * BSZ + b) * DM);
        } else if (MODE == 2) {
            aptr[v] = g_AV + (size_t)grow * K;
        } else {
            aptr[v] = A + (size_t)grow * K;
        }
    }
    const float* bptr[2]; int brow[2], bkc[2];
#pragma unroll
    for (int v = 0; v < 2; v++) {
        int idx = tid + v * 256;
        brow[v] = idx >> 3; bkc[v] = (idx & 7) * 4;
        bptr[v] = B + (size_t)(n0 + brow[v]) * K;
    }

    // ---- warp/fragment mapping
    const int wid = tid >> 5, lane = tid & 31;
    const int wm = wid >> 1;          // 0..3 : 32-row slab
    const int wn = wid & 1;           // 0..1 : 32-col slab
    const int gid = lane >> 2;        // 0..7
    const int tig = lane & 3;         // 0..3
    const int rm = wm * 32, rn = wn * 32;

    float acc[2][4][4];
#pragma unroll
    for (int mt = 0; mt < 2; mt++)
#pragma unroll
        for (int nt = 0; nt < 4; nt++)
#pragma unroll
            for (int r = 0; r < 4; r++) acc[mt][nt][r] = 0.f;

    float4 av[4], bv[2];
#pragma unroll
    for (int v = 0; v < 4; v++) av[v] = *(const float4*)(aptr[v] + akc[v]);
#pragma unroll
    for (int v = 0; v < 2; v++) bv[v] = *(const float4*)(bptr[v] + bkc[v]);

    for (int k0 = 0; k0 < K; k0 += 32) {
#pragma unroll
        for (int v = 0; v < 4; v++) {
            As[arow[v]][akc[v] + 0] = f2tf32(av[v].x);
            As[arow[v]][akc[v] + 1] = f2tf32(av[v].y);
            As[arow[v]][akc[v] + 2] = f2tf32(av[v].z);
            As[arow[v]][akc[v] + 3] = f2tf32(av[v].w);
        }
#pragma unroll
        for (int v = 0; v < 2; v++) {
            Bs[brow[v]][bkc[v] + 0] = f2tf32(bv[v].x);
            Bs[brow[v]][bkc[v] + 1] = f2tf32(bv[v].y);
            Bs[brow[v]][bkc[v] + 2] = f2tf32(bv[v].z);
            Bs[brow[v]][bkc[v] + 3] = f2tf32(bv[v].w);
        }
        __syncthreads();
        if (k0 + 32 < K) {
#pragma unroll
            for (int v = 0; v < 4; v++) av[v] = *(const float4*)(aptr[v] + k0 + 32 + akc[v]);
#pragma unroll
            for (int v = 0; v < 2; v++) bv[v] = *(const float4*)(bptr[v] + k0 + 32 + bkc[v]);
        }
#pragma unroll
        for (int kk = 0; kk < 32; kk += 8) {
            uint32_t afr[2][4], bfr[4][2];
#pragma unroll
            for (int mt = 0; mt < 2; mt++) {
                int r0 = rm + mt * 16 + gid;
                afr[mt][0] = As[r0][kk + tig];
                afr[mt][1] = As[r0 + 8][kk + tig];
                afr[mt][2] = As[r0][kk + tig + 4];
                afr[mt][3] = As[r0 + 8][kk + tig + 4];
            }
#pragma unroll
            for (int nt = 0; nt < 4; nt++) {
                int c0 = rn + nt * 8 + gid;
                bfr[nt][0] = Bs[c0][kk + tig];
                bfr[nt][1] = Bs[c0][kk + tig + 4];
            }
#pragma unroll
            for (int mt = 0; mt < 2; mt++)
#pragma unroll
                for (int nt = 0; nt < 4; nt++)
                    mma_tf32(acc[mt][nt], afr[mt], bfr[nt]);
        }
        __syncthreads();
    }

    // ---- epilogue scatter
#pragma unroll
    for (int mt = 0; mt < 2; mt++) {
#pragma unroll
        for (int nt = 0; nt < 4; nt++) {
#pragma unroll
            for (int r = 0; r < 4; r++) {
                int gr = m0 + rm + mt * 16 + gid + ((r >= 2) ? 8 : 0);
                int gc = n0 + rn + nt * 8 + tig * 2 + (r & 1);
                float v = acc[mt][nt][r];
                if (MODE == 0) {
                    int part = gc >> 10, hn = (gc >> 6) & 15, d = gc & 63;
                    int t = gr >> 2, b = gr & 3;
                    if (part == 0) {
                        if (t >= MLEN)
                            g_Q[(((size_t)(b * NH + hn)) * QLEN + (t - MLEN)) * DH + d] = v;
                    } else if (part == 1) {
                        g_K[(((size_t)(b * NH + hn)) * KLEN + t) * DH + d] = v;
                    } else {
                        g_V[(((size_t)(b * NH + hn)) * KLEN + t) * DH + d] = v;
                    }
                } else if (MODE == 1) {
                    int hn = gc >> 6, d = gc & 63;
                    g_R[((size_t)hn * KLEN + gr) * DH + d] = v;
                } else {
                    g_AO[(size_t)gr * DM + gc] = v;
                }
            }
        }
    }
}

// ---------------------------------------------------------------------------
// Fused attention v4 (unchanged from R8): 4x4 register blocking, fused
// stage1+stage2 d-loop, distributed c[p] GEMV, sliding BD window.
// ---------------------------------------------------------------------------
#define SWZ(d) ((((d) >> 2) & 7) << 2)

__global__ void __launch_bounds__(256, 2) attn_kernel(
    const float* __restrict__ rwb, const float* __restrict__ rrb)
{
    extern __shared__ float sm[];
    float* Qt    = sm;               // [d][i^swz]  64*68
    float* Ks    = Qt + 64 * 68;     // [d][j^swz]  64*68
    float* Rs    = Ks + 64 * 68;     // [d][p^swz]  64*68   (aliased by Vs [j][d])
    float* Bh    = Rs + 64 * 68;     // [i][0..127] 64*132  (cols 0..63 also Ps)
    float* cs    = Bh + 64 * 132;    // [132]
    float* diffs = cs + 132;         // [64]
    float* Vs    = Rs;               // alias

    const int i0 = blockIdx.x * 64;
    const int bn = blockIdx.y;
    const int b = bn >> 4, n = bn & 15;
    const int tid = threadIdx.x;
    const int tr = tid >> 4;     // 0..15 : i rows tr*4..+3
    const int tc = tid & 15;     // 0..15 : j / d cols tc*4..+3

    const float* Qg = g_Q + ((size_t)bn * QLEN + i0) * DH;
    const float* Kg = g_K + (size_t)bn * KLEN * DH;
    const float* Vg = g_V + (size_t)bn * KLEN * DH;
    const float* Rg = g_R + (size_t)n * KLEN * DH;

    for (int vv = tid; vv < 64 * 64 / 4; vv += 256) {
        int idx = vv * 4, i = idx >> 6, d = idx & 63;
        float4 q = *(const float4*)(Qg + i * DH + d);
        float4 u = *(const float4*)(rwb + n * DH + d);
        int ic = i ^ SWZ(d);
        Qt[(d + 0) * 68 + ic] = (q.x + u.x) * SCALE;
        Qt[(d + 1) * 68 + ic] = (q.y + u.y) * SCALE;
        Qt[(d + 2) * 68 + ic] = (q.z + u.z) * SCALE;
        Qt[(d + 3) * 68 + ic] = (q.w + u.w) * SCALE;
    }
    if (tid < 64) diffs[tid] = (rrb[n * DH + tid] - rwb[n * DH + tid]) * SCALE;

    const int rbase0 = QLEN - 64 - i0;
    for (int vv = tid; vv < 64 * 64 / 4; vv += 256) {
        int idx = vv * 4, rr = idx >> 6, d = idx & 63;
        float4 rv = *(const float4*)(Rg + (size_t)(rbase0 + rr) * DH + d);
        int rc = rr ^ SWZ(d);
        Rs[(d + 0) * 68 + rc] = rv.x; Rs[(d + 1) * 68 + rc] = rv.y;
        Rs[(d + 2) * 68 + rc] = rv.z; Rs[(d + 3) * 68 + rc] = rv.w;
    }
    __syncthreads();

    {
        float acc[4][4];
#pragma unroll
        for (int ii = 0; ii < 4; ii++)
#pragma unroll
            for (int jj = 0; jj < 4; jj++) acc[ii][jj] = 0.f;
#pragma unroll 4
        for (int d = 0; d < 64; d++) {
            const int swz = SWZ(d);
            float4 a = *(const float4*)&Qt[d * 68 + ((tr * 4) ^ swz)];
            float4 r = *(const float4*)&Rs[d * 68 + ((tc * 4) ^ swz)];
            float av[4] = {a.x, a.y, a.z, a.w};
            float rv[4] = {r.x, r.y, r.z, r.w};
#pragma unroll
            for (int ii = 0; ii < 4; ii++)
#pragma unroll
                for (int jj = 0; jj < 4; jj++) acc[ii][jj] += av[ii] * rv[jj];
        }
#pragma unroll
        for (int ii = 0; ii < 4; ii++)
            *(float4*)&Bh[(tr * 4 + ii) * 132 + 64 + tc * 4] = *(float4*)&acc[ii][0];
        int p = tid >> 2, seg = (tid & 3) * 16;
        float c = 0.f;
#pragma unroll 4
        for (int d = seg; d < seg + 16; d++)
            c += diffs[d] * Rs[d * 68 + (p ^ SWZ(d))];
        c += __shfl_xor_sync(0xffffffffu, c, 1);
        c += __shfl_xor_sync(0xffffffffu, c, 2);
        if ((tid & 3) == 0) cs[64 + p] = c;
    }

    float m[4], l[4], O[4][4];
#pragma unroll
    for (int ii = 0; ii < 4; ii++) {
        m[ii] = -1e30f; l[ii] = 0.f;
#pragma unroll
        for (int dd = 0; dd < 4; dd++) O[ii][dd] = 0.f;
    }

    const int njt = (MLEN + i0 + 63) / 64 + 1;

    for (int jt = 0; jt < njt; jt++) {
        const int j0 = jt * 64;
        const int rbase = j0 - i0 + (QLEN - 64);
        __syncthreads();

        for (int vv = tid; vv < 1024; vv += 256) {
            int row = vv >> 4, cg = vv & 15;
            *(float4*)&Bh[row * 132 + cg * 4] =
                *(const float4*)&Bh[row * 132 + 64 + cg * 4];
        }
        if (tid < 64) cs[tid] = cs[64 + tid];

        for (int vv = tid; vv < 64 * 64 / 4; vv += 256) {
            int idx = vv * 4, j = idx >> 6, d = idx & 63;
            float4 kv = *(const float4*)(Kg + (size_t)(j0 + j) * DH + d);
            int jc = j ^ SWZ(d);
            Ks[(d + 0) * 68 + jc] = kv.x; Ks[(d + 1) * 68 + jc] = kv.y;
            Ks[(d + 2) * 68 + jc] = kv.z; Ks[(d + 3) * 68 + jc] = kv.w;
        }
        for (int vv = tid; vv < 64 * 64 / 4; vv += 256) {
            int idx = vv * 4, rr = idx >> 6, d = idx & 63;
            int row = rbase + 64 + rr; if (row > KLEN - 1) row = KLEN - 1;
            float4 rv = *(const float4*)(Rg + (size_t)row * DH + d);
            int rc = rr ^ SWZ(d);
            Rs[(d + 0) * 68 + rc] = rv.x; Rs[(d + 1) * 68 + rc] = rv.y;
            Rs[(d + 2) * 68 + rc] = rv.z; Rs[(d + 3) * 68 + rc] = rv.w;
        }
        float4 vreg[4];
#pragma unroll
        for (int u = 0; u < 4; u++) {
            int idx = (tid + u * 256) * 4, j = idx >> 6, d = idx & 63;
            vreg[u] = *(const float4*)(Vg + (size_t)(j0 + j) * DH + d);
        }
        __syncthreads();

        float as4[4][4], ab4[4][4];
#pragma unroll
        for (int ii = 0; ii < 4; ii++)
#pragma unroll
            for (int jj = 0; jj < 4; jj++) { as4[ii][jj] = 0.f; ab4[ii][jj] = 0.f; }
#pragma unroll 4
        for (int d = 0; d < 64; d++) {
            const int swz = SWZ(d);
            float4 a = *(const float4*)&Qt[d * 68 + ((tr * 4) ^ swz)];
            float4 k = *(const float4*)&Ks[d * 68 + ((tc * 4) ^ swz)];
            float4 r = *(const float4*)&Rs[d * 68 + ((tc * 4) ^ swz)];
            float av[4] = {a.x, a.y, a.z, a.w};
            float kv[4] = {k.x, k.y, k.z, k.w};
            float rv[4] = {r.x, r.y, r.z, r.w};
#pragma unroll
            for (int ii = 0; ii < 4; ii++)
#pragma unroll
                for (int jj = 0; jj < 4; jj++) {
                    as4[ii][jj] += av[ii] * kv[jj];
                    ab4[ii][jj] += av[ii] * rv[jj];
                }
        }
#pragma unroll
        for (int ii = 0; ii < 4; ii++)
            *(float4*)&Bh[(tr * 4 + ii) * 132 + 64 + tc * 4] = *(float4*)&ab4[ii][0];
        {
            int p = tid >> 2, seg = (tid & 3) * 16;
            float c = 0.f;
#pragma unroll 4
            for (int d = seg; d < seg + 16; d++)
                c += diffs[d] * Rs[d * 68 + (p ^ SWZ(d))];
            c += __shfl_xor_sync(0xffffffffu, c, 1);
            c += __shfl_xor_sync(0xffffffffu, c, 2);
            if ((tid & 3) == 0) cs[64 + p] = c;
        }
        __syncthreads();

#pragma unroll
        for (int u = 0; u < 4; u++) {
            int idx = (tid + u * 256) * 4, j = idx >> 6, d = idx & 63;
            *(float4*)&Vs[j * 68 + d] = vreg[u];
        }

        float S[4][4];
#pragma unroll
        for (int ii = 0; ii < 4; ii++) {
            const int i = tr * 4 + ii;
            const float* bh = Bh + i * 132;
#pragma unroll
            for (int jj = 0; jj < 4; jj++) {
                int pl = tc * 4 + jj + 63 - i;
                S[ii][jj] = as4[ii][jj] + bh[pl] + cs[pl];
            }
        }
        if (j0 + 63 > MLEN + i0) {
#pragma unroll
            for (int ii = 0; ii < 4; ii++) {
                const int lim = MLEN + i0 + tr * 4 + ii - j0;
#pragma unroll
                for (int jj = 0; jj < 4; jj++)
                    if (tc * 4 + jj > lim) S[ii][jj] = -1e30f;
            }
        }
#pragma unroll
        for (int ii = 0; ii < 4; ii++) {
            float t = fmaxf(fmaxf(S[ii][0], S[ii][1]), fmaxf(S[ii][2], S[ii][3]));
            t = fmaxf(t, __shfl_xor_sync(0xffffffffu, t, 1));
            t = fmaxf(t, __shfl_xor_sync(0xffffffffu, t, 2));
            t = fmaxf(t, __shfl_xor_sync(0xffffffffu, t, 4));
            t = fmaxf(t, __shfl_xor_sync(0xffffffffu, t, 8));
            float mnew = fmaxf(m[ii], t);
            float corr = __expf(m[ii] - mnew);
            float s0 = 0.f;
#pragma unroll
            for (int jj = 0; jj < 4; jj++) {
                float p = __expf(S[ii][jj] - mnew); S[ii][jj] = p; s0 += p;
            }
            s0 += __shfl_xor_sync(0xffffffffu, s0, 1);
            s0 += __shfl_xor_sync(0xffffffffu, s0, 2);
            s0 += __shfl_xor_sync(0xffffffffu, s0, 4);
            s0 += __shfl_xor_sync(0xffffffffu, s0, 8);
            l[ii] = l[ii] * corr + s0;
            m[ii] = mnew;
#pragma unroll
            for (int dd = 0; dd < 4; dd++) O[ii][dd] *= corr;
        }

        __syncwarp();
#pragma unroll
        for (int ii = 0; ii < 4; ii++)
            *(float4*)&Bh[(tr * 4 + ii) * 132 + tc * 4] = *(float4*)&S[ii][0];
        __syncthreads();

#pragma unroll 2
        for (int j = 0; j < 64; j++) {
            float4 vv4 = *(const float4*)&Vs[j * 68 + tc * 4];
            float p0 = Bh[(tr * 4 + 0) * 132 + j];
            float p1 = Bh[(tr * 4 + 1) * 132 + j];
            float p2 = Bh[(tr * 4 + 2) * 132 + j];
            float p3 = Bh[(tr * 4 + 3) * 132 + j];
            O[0][0] += p0 * vv4.x; O[0][1] += p0 * vv4.y; O[0][2] += p0 * vv4.z; O[0][3] += p0 * vv4.w;
            O[1][0] += p1 * vv4.x; O[1][1] += p1 * vv4.y; O[1][2] += p1 * vv4.z; O[1][3] += p1 * vv4.w;
            O[2][0] += p2 * vv4.x; O[2][1] += p2 * vv4.y; O[2][2] += p2 * vv4.z; O[2][3] += p2 * vv4.w;
            O[3][0] += p3 * vv4.x; O[3][1] += p3 * vv4.y; O[3][2] += p3 * vv4.z; O[3][3] += p3 * vv4.w;
        }
    }

#pragma unroll
    for (int ii = 0; ii < 4; ii++) {
        const float inv = 1.f / l[ii];
        const int ig = i0 + tr * 4 + ii;
        float* op = g_AV + ((size_t)ig * BSZ + b) * DM + n * DH + tc * 4;
        *(float4*)op = make_float4(O[ii][0]*inv, O[ii][1]*inv, O[ii][2]*inv, O[ii][3]*inv);
    }
}

// ---------------------------------------------------------------------------
// Residual + LayerNorm
// ---------------------------------------------------------------------------
__global__ void __launch_bounds__(256) ln_kernel(
    const float* __restrict__ w, const float* __restrict__ g,
    const float* __restrict__ beta, float* __restrict__ out)
{
    const int row = blockIdx.x;
    const float* ao = g_AO + (size_t)row * DM;
    const float* wr = w    + (size_t)row * DM;
    const int tid = threadIdx.x;
    float x[4];
    float s = 0.f, ss = 0.f;
#pragma unroll
    for (int v = 0; v < 4; v++) {
        int c = tid + v * 256;
        float val = wr[c] + ao[c];
        x[v] = val; s += val; ss += val * val;
    }
#pragma unroll
    for (int o = 16; o; o >>= 1) {
        s  += __shfl_xor_sync(0xffffffffu, s,  o);
        ss += __shfl_xor_sync(0xffffffffu, ss, o);
    }
    __shared__ float sA[8], sB[8];
    int wid = tid >> 5, lane = tid & 31;
    if (lane == 0) { sA[wid] = s; sB[wid] = ss; }
    __syncthreads();
    if (wid == 0) {
        s  = (lane < 8) ? sA[lane] : 0.f;
        ss = (lane < 8) ? sB[lane] : 0.f;
#pragma unroll
        for (int o = 4; o; o >>= 1) {
            s  += __shfl_xor_sync(0xffffffffu, s,  o);
            ss += __shfl_xor_sync(0xffffffffu, ss, o);
        }
        if (lane == 0) { sA[0] = s; sB[0] = ss; }
    }
    __syncthreads();
    const float mu  = sA[0] * (1.f / DM);
    const float var = sB[0] * (1.f / DM) - mu * mu;
    const float rstd = rsqrtf(var + 1e-5f);
#pragma unroll
    for (int v = 0; v < 4; v++) {
        int c = tid + v * 256;
        out[(size_t)row * DM + c] = (x[v] - mu) * rstd * g[c] + beta[c];
    }
}

extern "C" void kernel_launch(void* const* d_in, const int* in_sizes, int n_in,
                              void* d_out, int out_size)
{
    const float* w     = (const float*)d_in[0];
    const float* r     = (const float*)d_in[1];
    const float* mems  = (const float*)d_in[2];
    // d_in[3] = attn_mask: analytic (j > MLEN + i), never read
    const float* qkv_w = (const float*)d_in[4];
    const float* r_w   = (const float*)d_in[5];
    const float* o_w   = (const float*)d_in[6];
    const float* rwb   = (const float*)d_in[7];
    const float* rrb   = (const float*)d_in[8];
    const float* ln_g  = (const float*)d_in[9];
    const float* ln_b  = (const float*)d_in[10];
    float* out = (float*)d_out;

    // 1) QKV projection over concat(mems, w)  [8192 x 3072 x 1024]
    tgemm_kernel<0><<<dim3(3072 / 64, (KLEN * BSZ) / 128), 256>>>(
        nullptr, qkv_w, w, mems, DM);
    // 2) relative-position keys  [2048 x 1024 x 1024]
    tgemm_kernel<1><<<dim3(DM / 64, KLEN / 128), 256>>>(
        r, r_w, nullptr, nullptr, DM);
    // 3) fused attention
    const int shmem = (64 * 68 * 3 + 64 * 132 + 132 + 64) * 4;  // 86800 B
    cudaFuncSetAttribute(attn_kernel, cudaFuncAttributeMaxDynamicSharedMemorySize, shmem);
    attn_kernel<<<dim3(QLEN / 64, BSZ * NH), 256, shmem>>>(rwb, rrb);
    // 4) output projection  [4096 x 1024 x 1024]
    tgemm_kernel<2><<<dim3(DM / 64, (QLEN * BSZ) / 128), 256>>>(
        nullptr, o_w, nullptr, nullptr, DM);
    // 5) residual + LayerNorm
    ln_kernel<<<QLEN * BSZ, 256>>>(w, ln_g, ln_b, out);
}

// round 10
// speedup vs baseline: 2.0071x; 1.4558x over previous
#include <cuda_runtime.h>
#include <math.h>
#include <stdint.h>

#define QLEN 1024
#define MLEN 1024
#define KLEN 2048
#define BSZ  4
#define DM   1024
#define NH   16
#define DH   64
#define SCALE 0.125f

// Scratch (device globals; no allocation allowed)
__device__ float g_Q [(size_t)BSZ*NH*QLEN*DH];   // [b][n][i][d]
__device__ float g_K [(size_t)BSZ*NH*KLEN*DH];   // [b][n][j][d]
__device__ float g_V [(size_t)BSZ*NH*KLEN*DH];   // [b][n][j][d]
__device__ float g_R [(size_t)NH*KLEN*DH];       // [n][p][d]
__device__ float g_AV[(size_t)QLEN*BSZ*DM];      // [i][b][n*64+d]
__device__ float g_AO[(size_t)QLEN*BSZ*DM];      // [i][b][c]

__device__ __forceinline__ uint32_t f2tf32(float x) {
    uint32_t u;
    asm("cvt.rna.tf32.f32 %0, %1;" : "=r"(u) : "f"(x));
    return u;
}

__device__ __forceinline__ void mma_tf32(float* c, const uint32_t* a, const uint32_t* b) {
    asm volatile(
        "mma.sync.aligned.m16n8k8.row.col.f32.tf32.tf32.f32 "
        "{%0,%1,%2,%3}, {%4,%5,%6,%7}, {%8,%9}, {%0,%1,%2,%3};"
        : "+f"(c[0]), "+f"(c[1]), "+f"(c[2]), "+f"(c[3])
        : "r"(a[0]), "r"(a[1]), "r"(a[2]), "r"(a[3]), "r"(b[0]), "r"(b[1]));
}

// ---------------------------------------------------------------------------
// TF32 tensor-core GEMM: C = A @ B^T. CTA tile 128x64, BK=32 (unchanged, R9).
// ---------------------------------------------------------------------------
template<int MODE>
__global__ void __launch_bounds__(256, 2) tgemm_kernel(
    const float* __restrict__ A, const float* __restrict__ B,
    const float* __restrict__ w, const float* __restrict__ mems, int K)
{
    __shared__ uint32_t As[128][36];
    __shared__ uint32_t Bs[64][36];
    const int tid = threadIdx.x;
    const int m0 = blockIdx.y * 128;
    const int n0 = blockIdx.x * 64;

    const float* aptr[4]; int arow[4], akc[4];
#pragma unroll
    for (int v = 0; v < 4; v++) {
        int idx = tid + v * 256;
        arow[v] = idx >> 3; akc[v] = (idx & 7) * 4;
        int grow = m0 + arow[v];
        if (MODE == 0) {
            int t = grow >> 2, b = grow & 3;
            aptr[v] = (t < MLEN) ? (mems + ((size_t)t * BSZ + b) * DM)
                                 : (w    + ((size_t)(t - MLEN) * BSZ + b) * DM);
        } else if (MODE == 2) {
            aptr[v] = g_AV + (size_t)grow * K;
        } else {
            aptr[v] = A + (size_t)grow * K;
        }
    }
    const float* bptr[2]; int brow[2], bkc[2];
#pragma unroll
    for (int v = 0; v < 2; v++) {
        int idx = tid + v * 256;
        brow[v] = idx >> 3; bkc[v] = (idx & 7) * 4;
        bptr[v] = B + (size_t)(n0 + brow[v]) * K;
    }

    const int wid = tid >> 5, lane = tid & 31;
    const int wm = wid >> 1;
    const int wn = wid & 1;
    const int gid = lane >> 2;
    const int tig = lane & 3;
    const int rm = wm * 32, rn = wn * 32;

    float acc[2][4][4];
#pragma unroll
    for (int mt = 0; mt < 2; mt++)
#pragma unroll
        for (int nt = 0; nt < 4; nt++)
#pragma unroll
            for (int r = 0; r < 4; r++) acc[mt][nt][r] = 0.f;

    float4 av[4], bv[2];
#pragma unroll
    for (int v = 0; v < 4; v++) av[v] = *(const float4*)(aptr[v] + akc[v]);
#pragma unroll
    for (int v = 0; v < 2; v++) bv[v] = *(const float4*)(bptr[v] + bkc[v]);

    for (int k0 = 0; k0 < K; k0 += 32) {
#pragma unroll
        for (int v = 0; v < 4; v++) {
            As[arow[v]][akc[v] + 0] = f2tf32(av[v].x);
            As[arow[v]][akc[v] + 1] = f2tf32(av[v].y);
            As[arow[v]][akc[v] + 2] = f2tf32(av[v].z);
            As[arow[v]][akc[v] + 3] = f2tf32(av[v].w);
        }
#pragma unroll
        for (int v = 0; v < 2; v++) {
            Bs[brow[v]][bkc[v] + 0] = f2tf32(bv[v].x);
            Bs[brow[v]][bkc[v] + 1] = f2tf32(bv[v].y);
            Bs[brow[v]][bkc[v] + 2] = f2tf32(bv[v].z);
            Bs[brow[v]][bkc[v] + 3] = f2tf32(bv[v].w);
        }
        __syncthreads();
        if (k0 + 32 < K) {
#pragma unroll
            for (int v = 0; v < 4; v++) av[v] = *(const float4*)(aptr[v] + k0 + 32 + akc[v]);
#pragma unroll
            for (int v = 0; v < 2; v++) bv[v] = *(const float4*)(bptr[v] + k0 + 32 + bkc[v]);
        }
#pragma unroll
        for (int kk = 0; kk < 32; kk += 8) {
            uint32_t afr[2][4], bfr[4][2];
#pragma unroll
            for (int mt = 0; mt < 2; mt++) {
                int r0 = rm + mt * 16 + gid;
                afr[mt][0] = As[r0][kk + tig];
                afr[mt][1] = As[r0 + 8][kk + tig];
                afr[mt][2] = As[r0][kk + tig + 4];
                afr[mt][3] = As[r0 + 8][kk + tig + 4];
            }
#pragma unroll
            for (int nt = 0; nt < 4; nt++) {
                int c0 = rn + nt * 8 + gid;
                bfr[nt][0] = Bs[c0][kk + tig];
                bfr[nt][1] = Bs[c0][kk + tig + 4];
            }
#pragma unroll
            for (int mt = 0; mt < 2; mt++)
#pragma unroll
                for (int nt = 0; nt < 4; nt++)
                    mma_tf32(acc[mt][nt], afr[mt], bfr[nt]);
        }
        __syncthreads();
    }

#pragma unroll
    for (int mt = 0; mt < 2; mt++) {
#pragma unroll
        for (int nt = 0; nt < 4; nt++) {
#pragma unroll
            for (int r = 0; r < 4; r++) {
                int gr = m0 + rm + mt * 16 + gid + ((r >= 2) ? 8 : 0);
                int gc = n0 + rn + nt * 8 + tig * 2 + (r & 1);
                float v = acc[mt][nt][r];
                if (MODE == 0) {
                    int part = gc >> 10, hn = (gc >> 6) & 15, d = gc & 63;
                    int t = gr >> 2, b = gr & 3;
                    if (part == 0) {
                        if (t >= MLEN)
                            g_Q[(((size_t)(b * NH + hn)) * QLEN + (t - MLEN)) * DH + d] = v;
                    } else if (part == 1) {
                        g_K[(((size_t)(b * NH + hn)) * KLEN + t) * DH + d] = v;
                    } else {
                        g_V[(((size_t)(b * NH + hn)) * KLEN + t) * DH + d] = v;
                    }
                } else if (MODE == 1) {
                    int hn = gc >> 6, d = gc & 63;
                    g_R[((size_t)hn * KLEN + gr) * DH + d] = v;
                } else {
                    g_AO[(size_t)gr * DM + gc] = v;
                }
            }
        }
    }
}

// ---------------------------------------------------------------------------
// Fused attention v5: tensor-core S/BD/PV via m16n8k8 tf32 mma.
// CTA = 64 q-rows x one (b,n). 8 warps as 4(m)x2(n); warp tile 16x32.
// Per j-tile: [S | BD_new] = Qu @ [K | R]^T (shared A-frags); S accums ->
// Ss smem; BD accums -> Bh[:,64:128] (sliding window, c[p] decomposition);
// scalar softmax phase (4 threads/row) with rel-shift gather; P -> Ss;
// O accums rescaled by corr[row], then PV mma with Vt (= V^T, aliases Rs).
// ---------------------------------------------------------------------------
__global__ void __launch_bounds__(256, 2) attn_kernel(
    const float* __restrict__ rwb, const float* __restrict__ rrb)
{
    extern __shared__ uint32_t smu[];
    uint32_t* Qu = smu;                     // [i][d] tf32  64*68
    uint32_t* Ks = Qu + 64 * 68;            // [j][d] tf32  64*68
    uint32_t* Rs = Ks + 64 * 68;            // [p][d] tf32  64*68 (alias Vt [d][j])
    float*    Ss = (float*)(Rs + 64 * 68);  // [i][j] f32   64*68 (S then P)
    float*    Bh = Ss + 64 * 68;            // [i][0..127]  64*132
    float*    cs = Bh + 64 * 132;           // [132]
    float*    diffs = cs + 132;             // [64]
    float*    corrs = diffs + 64;           // [64]
    float*    linv  = corrs + 64;           // [64]
    uint32_t* Vt = Rs;                      // alias

    const int i0 = blockIdx.x * 64;
    const int bn = blockIdx.y;
    const int b = bn >> 4, n = bn & 15;
    const int tid = threadIdx.x;
    const int wid = tid >> 5, lane = tid & 31;
    const int gid = lane >> 2, tig = lane & 3;
    const int wm = wid >> 1, wn = wid & 1;
    const int rm = wm * 16, rn = wn * 32;
    // softmax mapping
    const int il = tid >> 2;           // row 0..63
    const int qd = tid & 3;            // quad member
    const int jb = qd * 16;
    const int ig = i0 + il;

    const float* Qg = g_Q + ((size_t)bn * QLEN + i0) * DH;
    const float* Kg = g_K + (size_t)bn * KLEN * DH;
    const float* Vg = g_V + (size_t)bn * KLEN * DH;
    const float* Rg = g_R + (size_t)n * KLEN * DH;

    // ---- prologue: Qu (bias+scale folded, tf32), diffs, prime R chunk
    for (int vv = tid; vv < 1024; vv += 256) {
        int idx = vv * 4, i = idx >> 6, d = idx & 63;
        float4 q = *(const float4*)(Qg + i * DH + d);
        float4 u = *(const float4*)(rwb + n * DH + d);
        uint4 t;
        t.x = f2tf32((q.x + u.x) * SCALE); t.y = f2tf32((q.y + u.y) * SCALE);
        t.z = f2tf32((q.z + u.z) * SCALE); t.w = f2tf32((q.w + u.w) * SCALE);
        *(uint4*)&Qu[i * 68 + d] = t;
    }
    if (tid < 64) diffs[tid] = (rrb[n * DH + tid] - rwb[n * DH + tid]) * SCALE;

    const int rbase0 = QLEN - 64 - i0;   // in [0,960]
    for (int vv = tid; vv < 1024; vv += 256) {
        int idx = vv * 4, rr = idx >> 6, d = idx & 63;
        float4 rv = *(const float4*)(Rg + (size_t)(rbase0 + rr) * DH + d);
        uint4 t;
        t.x = f2tf32(rv.x); t.y = f2tf32(rv.y); t.z = f2tf32(rv.z); t.w = f2tf32(rv.w);
        *(uint4*)&Rs[rr * 68 + d] = t;
    }
    __syncthreads();

    // ---- prime: Bh[:,64:128] = Qu @ Rprime^T ; cs[64:128]
    {
        float badc[4][4];
#pragma unroll
        for (int nt = 0; nt < 4; nt++)
#pragma unroll
            for (int r = 0; r < 4; r++) badc[nt][r] = 0.f;
#pragma unroll
        for (int kk = 0; kk < 64; kk += 8) {
            uint32_t afr[4], bfr[2];
            afr[0] = Qu[(rm + gid) * 68 + kk + tig];
            afr[1] = Qu[(rm + gid + 8) * 68 + kk + tig];
            afr[2] = Qu[(rm + gid) * 68 + kk + tig + 4];
            afr[3] = Qu[(rm + gid + 8) * 68 + kk + tig + 4];
#pragma unroll
            for (int nt = 0; nt < 4; nt++) {
                bfr[0] = Rs[(rn + nt * 8 + gid) * 68 + kk + tig];
                bfr[1] = Rs[(rn + nt * 8 + gid) * 68 + kk + tig + 4];
                mma_tf32(badc[nt], afr, bfr);
            }
        }
#pragma unroll
        for (int nt = 0; nt < 4; nt++) {
            int c0 = 64 + rn + nt * 8 + tig * 2;
            Bh[(rm + gid) * 132 + c0]     = badc[nt][0];
            Bh[(rm + gid) * 132 + c0 + 1] = badc[nt][1];
            Bh[(rm + gid + 8) * 132 + c0]     = badc[nt][2];
            Bh[(rm + gid + 8) * 132 + c0 + 1] = badc[nt][3];
        }
        int p = tid >> 2, seg = (tid & 3) * 16;
        float c = 0.f;
#pragma unroll 4
        for (int d = seg; d < seg + 16; d++)
            c += diffs[d] * __uint_as_float(Rs[p * 68 + d]);
        c += __shfl_xor_sync(0xffffffffu, c, 1);
        c += __shfl_xor_sync(0xffffffffu, c, 2);
        if ((tid & 3) == 0) cs[64 + p] = c;
    }

    float m = -1e30f, l = 0.f;       // per softmax-thread (row il), quad-redundant
    float oacc[4][4];
#pragma unroll
    for (int nt = 0; nt < 4; nt++)
#pragma unroll
        for (int r = 0; r < 4; r++) oacc[nt][r] = 0.f;

    const int njt = (MLEN + i0 + 63) / 64 + 1;

    for (int jt = 0; jt < njt; jt++) {
        const int j0 = jt * 64;
        const int rbase = j0 - i0 + (QLEN - 64);
        __syncthreads();   // A: prev PV / prime reads done

        // slide BD window
        for (int vv = tid; vv < 1024; vv += 256) {
            int row = vv >> 4, cg = vv & 15;
            *(float4*)&Bh[row * 132 + cg * 4] =
                *(const float4*)&Bh[row * 132 + 64 + cg * 4];
        }
        if (tid < 64) cs[tid] = cs[64 + tid];

        // K tile + next R chunk (tf32, untransposed)
        for (int vv = tid; vv < 1024; vv += 256) {
            int idx = vv * 4, j = idx >> 6, d = idx & 63;
            float4 kv = *(const float4*)(Kg + (size_t)(j0 + j) * DH + d);
            uint4 t;
            t.x = f2tf32(kv.x); t.y = f2tf32(kv.y); t.z = f2tf32(kv.z); t.w = f2tf32(kv.w);
            *(uint4*)&Ks[j * 68 + d] = t;
        }
        for (int vv = tid; vv < 1024; vv += 256) {
            int idx = vv * 4, rr = idx >> 6, d = idx & 63;
            int row = rbase + 64 + rr; if (row > KLEN - 1) row = KLEN - 1;
            float4 rv = *(const float4*)(Rg + (size_t)row * DH + d);
            uint4 t;
            t.x = f2tf32(rv.x); t.y = f2tf32(rv.y); t.z = f2tf32(rv.z); t.w = f2tf32(rv.w);
            *(uint4*)&Rs[rr * 68 + d] = t;
        }
        // V prefetch (regs; stored to Vt after sync C)
        float4 vreg[4];
#pragma unroll
        for (int u = 0; u < 4; u++) {
            int idx = (tid + u * 256) * 4, j = idx >> 6, d = idx & 63;
            vreg[u] = *(const float4*)(Vg + (size_t)(j0 + j) * DH + d);
        }
        __syncthreads();   // B: K/R ready, window slid

        // ---- S + BD mma (shared A fragments)
        float sacc[4][4], badc[4][4];
#pragma unroll
        for (int nt = 0; nt < 4; nt++)
#pragma unroll
            for (int r = 0; r < 4; r++) { sacc[nt][r] = 0.f; badc[nt][r] = 0.f; }
#pragma unroll
        for (int kk = 0; kk < 64; kk += 8) {
            uint32_t afr[4], bfr[2];
            afr[0] = Qu[(rm + gid) * 68 + kk + tig];
            afr[1] = Qu[(rm + gid + 8) * 68 + kk + tig];
            afr[2] = Qu[(rm + gid) * 68 + kk + tig + 4];
            afr[3] = Qu[(rm + gid + 8) * 68 + kk + tig + 4];
#pragma unroll
            for (int nt = 0; nt < 4; nt++) {
                int c0 = (rn + nt * 8 + gid) * 68 + kk + tig;
                bfr[0] = Ks[c0]; bfr[1] = Ks[c0 + 4];
                mma_tf32(sacc[nt], afr, bfr);
                bfr[0] = Rs[c0]; bfr[1] = Rs[c0 + 4];
                mma_tf32(badc[nt], afr, bfr);
            }
        }
#pragma unroll
        for (int nt = 0; nt < 4; nt++) {
            int c0 = rn + nt * 8 + tig * 2;
            Ss[(rm + gid) * 68 + c0]     = sacc[nt][0];
            Ss[(rm + gid) * 68 + c0 + 1] = sacc[nt][1];
            Ss[(rm + gid + 8) * 68 + c0]     = sacc[nt][2];
            Ss[(rm + gid + 8) * 68 + c0 + 1] = sacc[nt][3];
            Bh[(rm + gid) * 132 + 64 + c0]     = badc[nt][0];
            Bh[(rm + gid) * 132 + 64 + c0 + 1] = badc[nt][1];
            Bh[(rm + gid + 8) * 132 + 64 + c0]     = badc[nt][2];
            Bh[(rm + gid + 8) * 132 + 64 + c0 + 1] = badc[nt][3];
        }
        {
            int p = tid >> 2, seg = (tid & 3) * 16;
            float c = 0.f;
#pragma unroll 4
            for (int d = seg; d < seg + 16; d++)
                c += diffs[d] * __uint_as_float(Rs[p * 68 + d]);
            c += __shfl_xor_sync(0xffffffffu, c, 1);
            c += __shfl_xor_sync(0xffffffffu, c, 2);
            if ((tid & 3) == 0) cs[64 + p] = c;
        }
        __syncthreads();   // C: Ss/Bh/cs ready; Rs free

        // ---- softmax phase (row il, 16 cols at jb)
        {
            float S[16];
#pragma unroll
            for (int x = 0; x < 16; x += 4)
                *(float4*)&S[x] = *(const float4*)&Ss[il * 68 + jb + x];
            const float* bh = Bh + il * 132 + (jb + 63 - il);
            const float* cc = cs + (jb + 63 - il);
#pragma unroll
            for (int x = 0; x < 16; x++) S[x] += bh[x] + cc[x];
            if (j0 + jb + 15 > MLEN + ig) {
#pragma unroll
                for (int x = 0; x < 16; x++)
                    if (j0 + jb + x > MLEN + ig) S[x] = -1e30f;
            }
            float t = S[0];
#pragma unroll
            for (int x = 1; x < 16; x++) t = fmaxf(t, S[x]);
            t = fmaxf(t, __shfl_xor_sync(0xffffffffu, t, 1));
            t = fmaxf(t, __shfl_xor_sync(0xffffffffu, t, 2));
            float mnew = fmaxf(m, t);
            float corr = __expf(m - mnew);
            float s0 = 0.f;
#pragma unroll
            for (int x = 0; x < 16; x++) { float p = __expf(S[x] - mnew); S[x] = p; s0 += p; }
            s0 += __shfl_xor_sync(0xffffffffu, s0, 1);
            s0 += __shfl_xor_sync(0xffffffffu, s0, 2);
            l = l * corr + s0;
            m = mnew;
#pragma unroll
            for (int x = 0; x < 16; x += 4)
                *(float4*)&Ss[il * 68 + jb + x] = *(const float4*)&S[x];
            if (qd == 0) corrs[il] = corr;
        }
        // Vt transpose stores (aliases Rs; Rs reads done at sync C)
#pragma unroll
        for (int u = 0; u < 4; u++) {
            int idx = (tid + u * 256) * 4, j = idx >> 6, d = idx & 63;
            Vt[(d + 0) * 68 + j] = f2tf32(vreg[u].x);
            Vt[(d + 1) * 68 + j] = f2tf32(vreg[u].y);
            Vt[(d + 2) * 68 + j] = f2tf32(vreg[u].z);
            Vt[(d + 3) * 68 + j] = f2tf32(vreg[u].w);
        }
        __syncthreads();   // D: P, corrs, Vt ready

        // ---- rescale O, then PV mma
        {
            float c0 = corrs[rm + gid];
            float c1 = corrs[rm + gid + 8];
#pragma unroll
            for (int nt = 0; nt < 4; nt++) {
                oacc[nt][0] *= c0; oacc[nt][1] *= c0;
                oacc[nt][2] *= c1; oacc[nt][3] *= c1;
            }
        }
#pragma unroll
        for (int kk = 0; kk < 64; kk += 8) {
            uint32_t afr[4], bfr[2];
            afr[0] = f2tf32(Ss[(rm + gid) * 68 + kk + tig]);
            afr[1] = f2tf32(Ss[(rm + gid + 8) * 68 + kk + tig]);
            afr[2] = f2tf32(Ss[(rm + gid) * 68 + kk + tig + 4]);
            afr[3] = f2tf32(Ss[(rm + gid + 8) * 68 + kk + tig + 4]);
#pragma unroll
            for (int nt = 0; nt < 4; nt++) {
                int c0 = (rn + nt * 8 + gid) * 68 + kk + tig;
                bfr[0] = Vt[c0]; bfr[1] = Vt[c0 + 4];
                mma_tf32(oacc[nt], afr, bfr);
            }
        }
    }

    // ---- epilogue: 1/l scaling + store
    if (qd == 0) linv[il] = 1.f / l;
    __syncthreads();
    {
        float i0s = linv[rm + gid];
        float i1s = linv[rm + gid + 8];
        int r0 = i0 + rm + gid, r1 = i0 + rm + gid + 8;
        float* base0 = g_AV + ((size_t)r0 * BSZ + b) * DM + n * DH;
        float* base1 = g_AV + ((size_t)r1 * BSZ + b) * DM + n * DH;
#pragma unroll
        for (int nt = 0; nt < 4; nt++) {
            int c = rn + nt * 8 + tig * 2;
            *(float2*)&base0[c] = make_float2(oacc[nt][0] * i0s, oacc[nt][1] * i0s);
            *(float2*)&base1[c] = make_float2(oacc[nt][2] * i1s, oacc[nt][3] * i1s);
        }
    }
}

// ---------------------------------------------------------------------------
// Residual + LayerNorm
// ---------------------------------------------------------------------------
__global__ void __launch_bounds__(256) ln_kernel(
    const float* __restrict__ w, const float* __restrict__ g,
    const float* __restrict__ beta, float* __restrict__ out)
{
    const int row = blockIdx.x;
    const float* ao = g_AO + (size_t)row * DM;
    const float* wr = w    + (size_t)row * DM;
    const int tid = threadIdx.x;
    float x[4];
    float s = 0.f, ss = 0.f;
#pragma unroll
    for (int v = 0; v < 4; v++) {
        int c = tid + v * 256;
        float val = wr[c] + ao[c];
        x[v] = val; s += val; ss += val * val;
    }
#pragma unroll
    for (int o = 16; o; o >>= 1) {
        s  += __shfl_xor_sync(0xffffffffu, s,  o);
        ss += __shfl_xor_sync(0xffffffffu, ss, o);
    }
    __shared__ float sA[8], sB[8];
    int wid = tid >> 5, lane = tid & 31;
    if (lane == 0) { sA[wid] = s; sB[wid] = ss; }
    __syncthreads();
    if (wid == 0) {
        s  = (lane < 8) ? sA[lane] : 0.f;
        ss = (lane < 8) ? sB[lane] : 0.f;
#pragma unroll
        for (int o = 4; o; o >>= 1) {
            s  += __shfl_xor_sync(0xffffffffu, s,  o);
            ss += __shfl_xor_sync(0xffffffffu, ss, o);
        }
        if (lane == 0) { sA[0] = s; sB[0] = ss; }
    }
    __syncthreads();
    const float mu  = sA[0] * (1.f / DM);
    const float var = sB[0] * (1.f / DM) - mu * mu;
    const float rstd = rsqrtf(var + 1e-5f);
#pragma unroll
    for (int v = 0; v < 4; v++) {
        int c = tid + v * 256;
        out[(size_t)row * DM + c] = (x[v] - mu) * rstd * g[c] + beta[c];
    }
}

extern "C" void kernel_launch(void* const* d_in, const int* in_sizes, int n_in,
                              void* d_out, int out_size)
{
    const float* w     = (const float*)d_in[0];
    const float* r     = (const float*)d_in[1];
    const float* mems  = (const float*)d_in[2];
    // d_in[3] = attn_mask: analytic (j > MLEN + i), never read
    const float* qkv_w = (const float*)d_in[4];
    const float* r_w   = (const float*)d_in[5];
    const float* o_w   = (const float*)d_in[6];
    const float* rwb   = (const float*)d_in[7];
    const float* rrb   = (const float*)d_in[8];
    const float* ln_g  = (const float*)d_in[9];
    const float* ln_b  = (const float*)d_in[10];
    float* out = (float*)d_out;

    // 1) QKV projection over concat(mems, w)
    tgemm_kernel<0><<<dim3(3072 / 64, (KLEN * BSZ) / 128), 256>>>(
        nullptr, qkv_w, w, mems, DM);
    // 2) relative-position keys
    tgemm_kernel<1><<<dim3(DM / 64, KLEN / 128), 256>>>(
        r, r_w, nullptr, nullptr, DM);
    // 3) fused attention (tensor-core)
    const int shmem = (64 * 68 * 4 + 64 * 132 + 132 + 64 * 3) * 4;  // 104720 B
    cudaFuncSetAttribute(attn_kernel, cudaFuncAttributeMaxDynamicSharedMemorySize, shmem);
    attn_kernel<<<dim3(QLEN / 64, BSZ * NH), 256, shmem>>>(rwb, rrb);
    // 4) output projection
    tgemm_kernel<2><<<dim3(DM / 64, (QLEN * BSZ) / 128), 256>>>(
        nullptr, o_w, nullptr, nullptr, DM);
    // 5) residual + LayerNorm
    ln_kernel<<<QLEN * BSZ, 256>>>(w, ln_g, ln_b, out);
}